// round 12
// baseline (speedup 1.0000x reference)
#include <cuda_runtime.h>
#include <cuda_bf16.h>
#include <math.h>

#define NN   4096
#define FF   512
#define HH   60
#define CC   4
#define CAP  64      // max nnz per row of sub_adj (mean ~8.2)

// scratch (device globals; referenced ONLY from device code — see R3 post-mortem)
__device__ float g_deg[NN];          // zero at load; reset by k_xw prologue each run
__device__ float g_dis[NN];
__device__ float g_self[NN];         // dis_i^2 self-loop weight
__device__ int   g_cnt[NN];
__device__ int   g_cols[NN * CAP];
__device__ float g_vals[NN * CAP];   // after k_norm: fully normalized edge weight
__device__ float g_Ta[NN * HH];
__device__ float g_Tb[NN * HH];

__device__ __forceinline__ void cp16(unsigned s, const void* g) {
    asm volatile("cp.async.cg.shared.global [%0], [%1], 16;\n" :: "r"(s), "l"(g));
}

// ---------------------------------------------------------------------------
// K1: scan sub_adj (67 MB, HBM floor ~8.5 us), warp-ballot edge compaction,
// gather P_vec at nonzeros, sigmoid, column-degree atomic accumulation.
__global__ void k_build(const float* __restrict__ adj, const float* __restrict__ pvec) {
    int warp = (blockIdx.x * blockDim.x + threadIdx.x) >> 5;
    int lane = threadIdx.x & 31;
    if (warp >= NN) return;
    const int row = warp;
    const float4* rp = reinterpret_cast<const float4*>(adj + (size_t)row * NN);
    int cnt = 0;
    #pragma unroll 4
    for (int it = 0; it < NN / 128; ++it) {
        float4 v = rp[it * 32 + lane];
        int jb = it * 128 + lane * 4;
        float vv[4] = {v.x, v.y, v.z, v.w};
        #pragma unroll
        for (int q = 0; q < 4; ++q) {
            bool nz = (vv[q] != 0.0f);
            unsigned m = __ballot_sync(0xffffffffu, nz);
            if (nz) {
                int j = jb + q;
                int slot = cnt + __popc(m & ((1u << lane) - 1u));
                int a = row > j ? row : j;
                int b = row > j ? j : row;
                float p = pvec[(size_t)a * (a + 1) / 2 + b];   // tril idx a(a+1)/2+b
                float s = vv[q] / (1.0f + expf(-p));            // sigmoid(p)*adj
                if (slot < CAP) {
                    g_cols[row * CAP + slot] = j;
                    g_vals[row * CAP + slot] = s;
                }
                atomicAdd(&g_deg[j], s);
            }
            cnt += __popc(m);
        }
    }
    if (lane == 0) g_cnt[row] = cnt < CAP ? cnt : CAP;
}

// ---------------------------------------------------------------------------
// K2: g_Ta = x @ W1 (4096x512 @ 512x60) — R4/R5 config (measured ~11us):
// 128 blocks x 256 threads, 2 rows/thread, cp.async double-buffer, f32x2,
// DIRECT float4 stores. Prologue finalizes g_dis and resets g_deg.
__global__ void __launch_bounds__(256) k_xw(const float* __restrict__ x,
                                            const float* __restrict__ W) {
    int gid = blockIdx.x * 256 + threadIdx.x;
    if (gid < NN) {
        g_dis[gid] = rsqrtf(g_deg[gid] + 1.0f);  // +1: identity self-loop
        g_deg[gid] = 0.0f;                       // reset for graph replay
    }

    __shared__ __align__(16) float As[2][32][36];
    __shared__ __align__(16) float Ws[2][32][64];

    const int t  = threadIdx.x;
    const int tx = t & 15;
    const int ty = t >> 4;
    const int r0 = blockIdx.x * 32;

    { int b = t >> 7, rr = (t >> 2) & 31, cc = 60 + (t & 3); Ws[b][rr][cc] = 0.0f; }

    const int arow = t >> 3;
    const int akk  = (t & 7) * 4;
    const int wk   = t >> 3;
    const int wc   = (t & 7) * 8;

    auto issue = [&](int tile, int buf) {
        int k0 = tile * 32;
        unsigned sA = (unsigned)__cvta_generic_to_shared(&As[buf][arow][akk]);
        cp16(sA, x + (size_t)(r0 + arow) * FF + k0 + akk);
        unsigned sW = (unsigned)__cvta_generic_to_shared(&Ws[buf][wk][wc]);
        cp16(sW, W + (size_t)(k0 + wk) * HH + wc);
        if (wc + 4 < HH)
            cp16(sW + 16, W + (size_t)(k0 + wk) * HH + wc + 4);
        asm volatile("cp.async.commit_group;\n");
    };

    unsigned long long acc[2][2] = {{0ull, 0ull}, {0ull, 0ull}};

    issue(0, 0);
    int buf = 0;
    for (int tile = 0; tile < FF / 32; ++tile) {
        __syncthreads();
        if (tile < FF / 32 - 1) {
            issue(tile + 1, buf ^ 1);
            asm volatile("cp.async.wait_group 1;\n");
        } else {
            asm volatile("cp.async.wait_group 0;\n");
        }
        __syncthreads();
        #pragma unroll
        for (int k = 0; k < 32; ++k) {
            unsigned a0 = __float_as_uint(As[buf][2 * ty + 0][k]);
            unsigned a1 = __float_as_uint(As[buf][2 * ty + 1][k]);
            unsigned long long pa0, pa1;
            asm("mov.b64 %0, {%1, %1};" : "=l"(pa0) : "r"(a0));
            asm("mov.b64 %0, {%1, %1};" : "=l"(pa1) : "r"(a1));
            ulonglong2 w = *reinterpret_cast<const ulonglong2*>(&Ws[buf][k][4 * tx]);
            asm("fma.rn.f32x2 %0, %1, %2, %0;" : "+l"(acc[0][0]) : "l"(pa0), "l"(w.x));
            asm("fma.rn.f32x2 %0, %1, %2, %0;" : "+l"(acc[0][1]) : "l"(pa0), "l"(w.y));
            asm("fma.rn.f32x2 %0, %1, %2, %0;" : "+l"(acc[1][0]) : "l"(pa1), "l"(w.x));
            asm("fma.rn.f32x2 %0, %1, %2, %0;" : "+l"(acc[1][1]) : "l"(pa1), "l"(w.y));
        }
        buf ^= 1;
    }

    if (4 * tx < HH) {
        #pragma unroll
        for (int i = 0; i < 2; ++i) {
            unsigned lo0, hi0, lo1, hi1;
            asm("mov.b64 {%0, %1}, %2;" : "=r"(lo0), "=r"(hi0) : "l"(acc[i][0]));
            asm("mov.b64 {%0, %1}, %2;" : "=r"(lo1), "=r"(hi1) : "l"(acc[i][1]));
            float4 o = make_float4(__uint_as_float(lo0), __uint_as_float(hi0),
                                   __uint_as_float(lo1), __uint_as_float(hi1));
            int r = r0 + 2 * ty + i;
            *reinterpret_cast<float4*>(&g_Ta[(size_t)r * HH + 4 * tx]) = o;
        }
    }
}

// ---------------------------------------------------------------------------
// K3: fold D^{-1/2}: g_vals *= dis_i*dis_j; g_self = dis_i^2.
__global__ void k_norm() {
    int gid = blockIdx.x * 256 + threadIdx.x;
    int row = gid >> 4, le = gid & 15;
    if (row >= NN) return;
    float di = g_dis[row];
    int cnt = g_cnt[row];
    for (int e = le; e < cnt; e += 16)
        g_vals[row * CAP + e] *= di * g_dis[g_cols[row * CAP + e]];
    if (le == 0) g_self[row] = di * di;
}

// ---------------------------------------------------------------------------
// K4: fused layer v4. Gather: 8 groups x 64 lanes (1 col/lane, max latency
// parallelism). Dense: WARP-PER-ROW f32x2 — warp w (<8) computes row w, lane p
// computes col-pair (2p,2p+1) via LDS.64 + FFMA2 on 64-col-padded Ws.
// Halves dense-phase warp-instructions vs scalar (the measured binder).
__global__ void __launch_bounds__(512) k_layer(int src, const float* __restrict__ bias,
                                               const float* __restrict__ Wnext) {
    const float* __restrict__ Tin = src ? g_Tb : g_Ta;
    float* __restrict__ Tout      = src ? g_Ta : g_Tb;
    __shared__ __align__(16) float Ws[HH][64];    // 64-padded; cols 60..63 zero
    __shared__ float hs[8][HH];
    int t = threadIdx.x, c = t & 63, g = t >> 6;
    int row = blockIdx.x * 8 + g;

    // stage padded Ws via cp.async: 960 16B-chunks; chunk = k*16 + j.
    // j<15: copy Wnext[k][4j..4j+3] (Wnext row stride 240B = 15 chunks, aligned).
    // j==15: zero pad.
    {
        unsigned base = (unsigned)__cvta_generic_to_shared(&Ws[0][0]);
        #pragma unroll
        for (int s = 0; s < 2; ++s) {
            int chunk = t + s * 512;
            if (chunk < 960) {
                int k = chunk >> 4, j = chunk & 15;
                if (j < 15) cp16(base + chunk * 16, Wnext + k * HH + j * 4);
                else *reinterpret_cast<float4*>(&Ws[k][60]) = make_float4(0.f, 0.f, 0.f, 0.f);
            }
        }
        asm volatile("cp.async.commit_group;\n");
    }

    if (c < HH) {
        const int*   cp = &g_cols[row * CAP];
        const float* vp = &g_vals[row * CAP];
        int cnt = g_cnt[row];
        float a0 = g_self[row] * Tin[row * HH + c];
        float a1 = 0.f, a2 = 0.f, a3 = 0.f;
        int e = 0;
        for (; e + 4 <= cnt; e += 4) {
            int4   cc = *reinterpret_cast<const int4*>(&cp[e]);
            float4 ww = *reinterpret_cast<const float4*>(&vp[e]);
            a0 += ww.x * Tin[cc.x * HH + c];
            a1 += ww.y * Tin[cc.y * HH + c];
            a2 += ww.z * Tin[cc.z * HH + c];
            a3 += ww.w * Tin[cc.w * HH + c];
        }
        for (; e < cnt; ++e) a0 += vp[e] * Tin[cp[e] * HH + c];
        hs[g][c] = fmaxf((a0 + a1) + (a2 + a3) + bias[c], 0.0f);
    }
    asm volatile("cp.async.wait_group 0;\n");
    __syncthreads();

    // dense: warp w < 8 handles row w of this block; lane p -> cols 2p,2p+1
    int w = t >> 5, p = t & 31;
    if (w < 8) {
        unsigned long long acc = 0ull;
        #pragma unroll
        for (int k = 0; k < HH; ++k) {
            unsigned h = __float_as_uint(hs[w][k]);
            unsigned long long ph;
            asm("mov.b64 %0, {%1, %1};" : "=l"(ph) : "r"(h));
            unsigned long long wv = *reinterpret_cast<const unsigned long long*>(&Ws[k][2 * p]);
            asm("fma.rn.f32x2 %0, %1, %2, %0;" : "+l"(acc) : "l"(ph), "l"(wv));
        }
        if (p < 30) {
            unsigned lo, hi;
            asm("mov.b64 {%0, %1}, %2;" : "=r"(lo), "=r"(hi) : "l"(acc));
            *reinterpret_cast<float2*>(&Tout[(blockIdx.x * 8 + w) * HH + 2 * p]) =
                make_float2(__uint_as_float(lo), __uint_as_float(hi));
        }
    }
}

// ---------------------------------------------------------------------------
// K5: final: H3 = SpMM(g_Ta)+b3; logits = H3 @ lin_w + lin_b; log_softmax.
__global__ void __launch_bounds__(512) k_final(const float* __restrict__ b3,
                                               const float* __restrict__ lw,
                                               const float* __restrict__ lb,
                                               float* __restrict__ out) {
    const float* __restrict__ Tin = g_Ta;
    __shared__ float lws[HH * CC];
    __shared__ float hs[8][HH];
    __shared__ float lg[8][CC];
    int t = threadIdx.x, c = t & 63, g = t >> 6;
    int row = blockIdx.x * 8 + g;
    if (t < HH * CC) lws[t] = lw[t];

    if (c < HH) {
        const int*   cp = &g_cols[row * CAP];
        const float* vp = &g_vals[row * CAP];
        int cnt = g_cnt[row];
        float a0 = g_self[row] * Tin[row * HH + c];
        float a1 = 0.f, a2 = 0.f, a3 = 0.f;
        int e = 0;
        for (; e + 4 <= cnt; e += 4) {
            int4   cc = *reinterpret_cast<const int4*>(&cp[e]);
            float4 ww = *reinterpret_cast<const float4*>(&vp[e]);
            a0 += ww.x * Tin[cc.x * HH + c];
            a1 += ww.y * Tin[cc.y * HH + c];
            a2 += ww.z * Tin[cc.z * HH + c];
            a3 += ww.w * Tin[cc.w * HH + c];
        }
        for (; e < cnt; ++e) a0 += vp[e] * Tin[cp[e] * HH + c];
        hs[g][c] = (a0 + a1) + (a2 + a3) + b3[c];
    }
    __syncthreads();
    if (c < CC) {
        float o = lb[c];
        #pragma unroll
        for (int k = 0; k < HH; ++k)
            o += hs[g][k] * lws[k * CC + c];
        lg[g][c] = o;
    }
    __syncthreads();
    if (c < CC) {
        float m = fmaxf(fmaxf(lg[g][0], lg[g][1]), fmaxf(lg[g][2], lg[g][3]));
        float s = expf(lg[g][0] - m) + expf(lg[g][1] - m) +
                  expf(lg[g][2] - m) + expf(lg[g][3] - m);
        out[(size_t)row * CC + c] = lg[g][c] - m - logf(s);
    }
}

// ---------------------------------------------------------------------------
// Inputs resolved BY ELEMENT COUNT; same-size ties by relative order.
extern "C" void kernel_launch(void* const* d_in, const int* in_sizes, int n_in,
                              void* d_out, int out_size) {
    const float *x = 0, *adj = 0, *pvec = 0, *W1 = 0, *b1 = 0, *W2 = 0, *b2 = 0,
                *W3 = 0, *b3 = 0, *lin_w = 0, *lin_b = 0;
    int nb = 0, nw = 0;
    for (int i = 0; i < n_in; ++i) {
        const float* p = (const float*)d_in[i];
        switch (in_sizes[i]) {
            case NN * FF:            x = p;    break;
            case NN * NN:            adj = p;  break;
            case (NN * (NN + 1)) / 2: pvec = p; break;
            case FF * HH:            W1 = p;   break;
            case HH * HH:
                if (nw == 0) W2 = p; else W3 = p;
                ++nw; break;
            case HH:
                if (nb == 0) b1 = p; else if (nb == 1) b2 = p; else b3 = p;
                ++nb; break;
            case HH * CC:            lin_w = p; break;
            case CC:                 lin_b = p; break;
            default: break;
        }
    }
    float* out = (float*)d_out;

    k_build<<<NN / 8, 256>>>(adj, pvec);       // 1 warp/row; accumulates g_deg
    k_xw<<<NN / 32, 256>>>(x, W1);             // g_Ta = x@W1 (+ dis finalize)
    k_norm<<<NN * 16 / 256, 256>>>();          // fold D^{-1/2} into edges
    k_layer<<<NN / 8, 512>>>(0, b1, W2);       // g_Ta -> g_Tb
    k_layer<<<NN / 8, 512>>>(1, b2, W3);       // g_Tb -> g_Ta
    k_final<<<NN / 8, 512>>>(b3, lin_w, lin_b, out);
}

// round 13
// speedup vs baseline: 1.1084x; 1.1084x over previous
#include <cuda_runtime.h>
#include <cuda_bf16.h>
#include <math.h>

#define NN   4096
#define FF   512
#define HH   60
#define CC   4
#define CAP  64      // max nnz per row of sub_adj (mean ~8.2)

// scratch (device globals; referenced ONLY from device code — see R3 post-mortem)
__device__ float g_deg[NN];          // zero at load; reset by k_xw prologue each run
__device__ float g_dis[NN];
__device__ float g_self[NN];         // dis_i^2 self-loop weight
__device__ int   g_cnt[NN];
__device__ int   g_cols[NN * CAP];
__device__ float g_vals[NN * CAP];   // after k_norm: fully normalized edge weight
__device__ float g_Ta[NN * HH];
__device__ float g_Tb[NN * HH];

__device__ __forceinline__ void cp16(unsigned s, const void* g) {
    asm volatile("cp.async.cg.shared.global [%0], [%1], 16;\n" :: "r"(s), "l"(g));
}

// ---------------------------------------------------------------------------
// K1: scan sub_adj (67 MB, HBM floor ~8.5 us), warp-ballot edge compaction,
// gather P_vec at nonzeros, sigmoid, column-degree atomic accumulation.
__global__ void k_build(const float* __restrict__ adj, const float* __restrict__ pvec) {
    int warp = (blockIdx.x * blockDim.x + threadIdx.x) >> 5;
    int lane = threadIdx.x & 31;
    if (warp >= NN) return;
    const int row = warp;
    const float4* rp = reinterpret_cast<const float4*>(adj + (size_t)row * NN);
    int cnt = 0;
    #pragma unroll 4
    for (int it = 0; it < NN / 128; ++it) {
        float4 v = rp[it * 32 + lane];
        int jb = it * 128 + lane * 4;
        float vv[4] = {v.x, v.y, v.z, v.w};
        #pragma unroll
        for (int q = 0; q < 4; ++q) {
            bool nz = (vv[q] != 0.0f);
            unsigned m = __ballot_sync(0xffffffffu, nz);
            if (nz) {
                int j = jb + q;
                int slot = cnt + __popc(m & ((1u << lane) - 1u));
                int a = row > j ? row : j;
                int b = row > j ? j : row;
                float p = pvec[(size_t)a * (a + 1) / 2 + b];   // tril idx a(a+1)/2+b
                float s = vv[q] / (1.0f + expf(-p));            // sigmoid(p)*adj
                if (slot < CAP) {
                    g_cols[row * CAP + slot] = j;
                    g_vals[row * CAP + slot] = s;
                }
                atomicAdd(&g_deg[j], s);
            }
            cnt += __popc(m);
        }
    }
    if (lane == 0) g_cnt[row] = cnt < CAP ? cnt : CAP;
}

// ---------------------------------------------------------------------------
// K2: g_Ta = x @ W1 — R4/R5 proven config: 128 blocks x 256 threads,
// cp.async double-buffer, f32x2, direct float4 stores.
__global__ void __launch_bounds__(256) k_xw(const float* __restrict__ x,
                                            const float* __restrict__ W) {
    int gid = blockIdx.x * 256 + threadIdx.x;
    if (gid < NN) {
        g_dis[gid] = rsqrtf(g_deg[gid] + 1.0f);  // +1: identity self-loop
        g_deg[gid] = 0.0f;                       // reset for graph replay
    }

    __shared__ __align__(16) float As[2][32][36];
    __shared__ __align__(16) float Ws[2][32][64];

    const int t  = threadIdx.x;
    const int tx = t & 15;
    const int ty = t >> 4;
    const int r0 = blockIdx.x * 32;

    { int b = t >> 7, rr = (t >> 2) & 31, cc = 60 + (t & 3); Ws[b][rr][cc] = 0.0f; }

    const int arow = t >> 3;
    const int akk  = (t & 7) * 4;
    const int wk   = t >> 3;
    const int wc   = (t & 7) * 8;

    auto issue = [&](int tile, int buf) {
        int k0 = tile * 32;
        unsigned sA = (unsigned)__cvta_generic_to_shared(&As[buf][arow][akk]);
        cp16(sA, x + (size_t)(r0 + arow) * FF + k0 + akk);
        unsigned sW = (unsigned)__cvta_generic_to_shared(&Ws[buf][wk][wc]);
        cp16(sW, W + (size_t)(k0 + wk) * HH + wc);
        if (wc + 4 < HH)
            cp16(sW + 16, W + (size_t)(k0 + wk) * HH + wc + 4);
        asm volatile("cp.async.commit_group;\n");
    };

    unsigned long long acc[2][2] = {{0ull, 0ull}, {0ull, 0ull}};

    issue(0, 0);
    int buf = 0;
    for (int tile = 0; tile < FF / 32; ++tile) {
        __syncthreads();
        if (tile < FF / 32 - 1) {
            issue(tile + 1, buf ^ 1);
            asm volatile("cp.async.wait_group 1;\n");
        } else {
            asm volatile("cp.async.wait_group 0;\n");
        }
        __syncthreads();
        #pragma unroll
        for (int k = 0; k < 32; ++k) {
            unsigned a0 = __float_as_uint(As[buf][2 * ty + 0][k]);
            unsigned a1 = __float_as_uint(As[buf][2 * ty + 1][k]);
            unsigned long long pa0, pa1;
            asm("mov.b64 %0, {%1, %1};" : "=l"(pa0) : "r"(a0));
            asm("mov.b64 %0, {%1, %1};" : "=l"(pa1) : "r"(a1));
            ulonglong2 w = *reinterpret_cast<const ulonglong2*>(&Ws[buf][k][4 * tx]);
            asm("fma.rn.f32x2 %0, %1, %2, %0;" : "+l"(acc[0][0]) : "l"(pa0), "l"(w.x));
            asm("fma.rn.f32x2 %0, %1, %2, %0;" : "+l"(acc[0][1]) : "l"(pa0), "l"(w.y));
            asm("fma.rn.f32x2 %0, %1, %2, %0;" : "+l"(acc[1][0]) : "l"(pa1), "l"(w.x));
            asm("fma.rn.f32x2 %0, %1, %2, %0;" : "+l"(acc[1][1]) : "l"(pa1), "l"(w.y));
        }
        buf ^= 1;
    }

    if (4 * tx < HH) {
        #pragma unroll
        for (int i = 0; i < 2; ++i) {
            unsigned lo0, hi0, lo1, hi1;
            asm("mov.b64 {%0, %1}, %2;" : "=r"(lo0), "=r"(hi0) : "l"(acc[i][0]));
            asm("mov.b64 {%0, %1}, %2;" : "=r"(lo1), "=r"(hi1) : "l"(acc[i][1]));
            float4 o = make_float4(__uint_as_float(lo0), __uint_as_float(hi0),
                                   __uint_as_float(lo1), __uint_as_float(hi1));
            int r = r0 + 2 * ty + i;
            *reinterpret_cast<float4*>(&g_Ta[(size_t)r * HH + 4 * tx]) = o;
        }
    }
}

// ---------------------------------------------------------------------------
// K3: fold D^{-1/2}: g_vals *= dis_i*dis_j; g_self = dis_i^2.
__global__ void k_norm() {
    int gid = blockIdx.x * 256 + threadIdx.x;
    int row = gid >> 4, le = gid & 15;
    if (row >= NN) return;
    float di = g_dis[row];
    int cnt = g_cnt[row];
    for (int e = le; e < cnt; e += 16)
        g_vals[row * CAP + e] *= di * g_dis[g_cols[row * CAP + e]];
    if (le == 0) g_self[row] = di * di;
}

// ---------------------------------------------------------------------------
// K4: fused layer v5. GATHER IS THE BOTTLENECK (latency-exposed scalar LDGs):
// now float4 gather — 64 lanes/row = 4 edge-subgroups x 16 col-lanes (15
// active, 4 cols each). 4x fewer loads, 4x more bytes each; partials reduced
// via smem in fixed order (deterministic). Dense: warp-per-row f32x2.
__global__ void __launch_bounds__(512) k_layer(int src, const float* __restrict__ bias,
                                               const float* __restrict__ Wnext) {
    const float* __restrict__ Tin = src ? g_Tb : g_Ta;
    float* __restrict__ Tout      = src ? g_Ta : g_Tb;
    __shared__ __align__(16) float Ws[HH][64];    // 64-padded; cols 60..63 zero
    __shared__ __align__(16) float4 red[8][4][16];
    __shared__ float hs[8][HH];
    int t = threadIdx.x;
    int g = t >> 6, c = t & 63, sub = c >> 4, cl = c & 15;
    int row = blockIdx.x * 8 + g;

    // stage padded Ws via cp.async (R12 coverage: all 960 chunks)
    {
        unsigned base = (unsigned)__cvta_generic_to_shared(&Ws[0][0]);
        #pragma unroll
        for (int s = 0; s < 2; ++s) {
            int chunk = t + s * 512;
            if (chunk < 960) {
                int k = chunk >> 4, j = chunk & 15;
                if (j < 15) cp16(base + chunk * 16, Wnext + k * HH + j * 4);
                else *reinterpret_cast<float4*>(&Ws[k][60]) = make_float4(0.f, 0.f, 0.f, 0.f);
            }
        }
        asm volatile("cp.async.commit_group;\n");
    }

    // float4 gather, 4-way edge-parallel
    float4 acc = make_float4(0.f, 0.f, 0.f, 0.f);
    {
        const int*   cp = &g_cols[row * CAP];
        const float* vp = &g_vals[row * CAP];
        int cnt = g_cnt[row];
        if (cl < 15) {
            if (sub == 0) {
                float s = g_self[row];
                float4 tv = *reinterpret_cast<const float4*>(&Tin[row * HH + cl * 4]);
                acc.x = s * tv.x; acc.y = s * tv.y; acc.z = s * tv.z; acc.w = s * tv.w;
            }
            for (int e = sub; e < cnt; e += 4) {
                float wv = vp[e];
                float4 tv = *reinterpret_cast<const float4*>(&Tin[cp[e] * HH + cl * 4]);
                acc.x += wv * tv.x; acc.y += wv * tv.y;
                acc.z += wv * tv.z; acc.w += wv * tv.w;
            }
        }
    }
    red[g][sub][cl] = acc;
    asm volatile("cp.async.wait_group 0;\n");
    __syncthreads();
    if (sub == 0 && cl < 15) {
        float4 r0 = red[g][0][cl], r1 = red[g][1][cl],
               r2 = red[g][2][cl], r3 = red[g][3][cl];
        float4 bb = *reinterpret_cast<const float4*>(&bias[cl * 4]);
        hs[g][cl * 4 + 0] = fmaxf(((r0.x + r1.x) + (r2.x + r3.x)) + bb.x, 0.f);
        hs[g][cl * 4 + 1] = fmaxf(((r0.y + r1.y) + (r2.y + r3.y)) + bb.y, 0.f);
        hs[g][cl * 4 + 2] = fmaxf(((r0.z + r1.z) + (r2.z + r3.z)) + bb.z, 0.f);
        hs[g][cl * 4 + 3] = fmaxf(((r0.w + r1.w) + (r2.w + r3.w)) + bb.w, 0.f);
    }
    __syncthreads();

    // dense: warp w < 8 handles row w; lane p -> cols 2p,2p+1 (f32x2)
    int w = t >> 5, p = t & 31;
    if (w < 8) {
        unsigned long long acc2 = 0ull;
        #pragma unroll
        for (int k = 0; k < HH; ++k) {
            unsigned h = __float_as_uint(hs[w][k]);
            unsigned long long ph;
            asm("mov.b64 %0, {%1, %1};" : "=l"(ph) : "r"(h));
            unsigned long long wv = *reinterpret_cast<const unsigned long long*>(&Ws[k][2 * p]);
            asm("fma.rn.f32x2 %0, %1, %2, %0;" : "+l"(acc2) : "l"(ph), "l"(wv));
        }
        if (p < 30) {
            unsigned lo, hi;
            asm("mov.b64 {%0, %1}, %2;" : "=r"(lo), "=r"(hi) : "l"(acc2));
            *reinterpret_cast<float2*>(&Tout[(blockIdx.x * 8 + w) * HH + 2 * p]) =
                make_float2(__uint_as_float(lo), __uint_as_float(hi));
        }
    }
}

// ---------------------------------------------------------------------------
// K5: final with the same float4 gather; then logits (H3 @ lin_w + lin_b) and
// log_softmax.
__global__ void __launch_bounds__(512) k_final(const float* __restrict__ b3,
                                               const float* __restrict__ lw,
                                               const float* __restrict__ lb,
                                               float* __restrict__ out) {
    const float* __restrict__ Tin = g_Ta;
    __shared__ float lws[HH * CC];
    __shared__ __align__(16) float4 red[8][4][16];
    __shared__ float hs[8][HH];
    __shared__ float lg[8][CC];
    int t = threadIdx.x;
    int g = t >> 6, c = t & 63, sub = c >> 4, cl = c & 15;
    int row = blockIdx.x * 8 + g;
    if (t < HH * CC) lws[t] = lw[t];

    float4 acc = make_float4(0.f, 0.f, 0.f, 0.f);
    {
        const int*   cp = &g_cols[row * CAP];
        const float* vp = &g_vals[row * CAP];
        int cnt = g_cnt[row];
        if (cl < 15) {
            if (sub == 0) {
                float s = g_self[row];
                float4 tv = *reinterpret_cast<const float4*>(&Tin[row * HH + cl * 4]);
                acc.x = s * tv.x; acc.y = s * tv.y; acc.z = s * tv.z; acc.w = s * tv.w;
            }
            for (int e = sub; e < cnt; e += 4) {
                float wv = vp[e];
                float4 tv = *reinterpret_cast<const float4*>(&Tin[cp[e] * HH + cl * 4]);
                acc.x += wv * tv.x; acc.y += wv * tv.y;
                acc.z += wv * tv.z; acc.w += wv * tv.w;
            }
        }
    }
    red[g][sub][cl] = acc;
    __syncthreads();
    if (sub == 0 && cl < 15) {
        float4 r0 = red[g][0][cl], r1 = red[g][1][cl],
               r2 = red[g][2][cl], r3 = red[g][3][cl];
        float4 bb = *reinterpret_cast<const float4*>(&b3[cl * 4]);
        hs[g][cl * 4 + 0] = ((r0.x + r1.x) + (r2.x + r3.x)) + bb.x;
        hs[g][cl * 4 + 1] = ((r0.y + r1.y) + (r2.y + r3.y)) + bb.y;
        hs[g][cl * 4 + 2] = ((r0.z + r1.z) + (r2.z + r3.z)) + bb.z;
        hs[g][cl * 4 + 3] = ((r0.w + r1.w) + (r2.w + r3.w)) + bb.w;
    }
    __syncthreads();
    if (c < CC) {
        float o = lb[c];
        #pragma unroll
        for (int k = 0; k < HH; ++k)
            o += hs[g][k] * lws[k * CC + c];
        lg[g][c] = o;
    }
    __syncthreads();
    if (c < CC) {
        float m = fmaxf(fmaxf(lg[g][0], lg[g][1]), fmaxf(lg[g][2], lg[g][3]));
        float s = expf(lg[g][0] - m) + expf(lg[g][1] - m) +
                  expf(lg[g][2] - m) + expf(lg[g][3] - m);
        out[(size_t)row * CC + c] = lg[g][c] - m - logf(s);
    }
}

// ---------------------------------------------------------------------------
// Inputs resolved BY ELEMENT COUNT; same-size ties by relative order.
extern "C" void kernel_launch(void* const* d_in, const int* in_sizes, int n_in,
                              void* d_out, int out_size) {
    const float *x = 0, *adj = 0, *pvec = 0, *W1 = 0, *b1 = 0, *W2 = 0, *b2 = 0,
                *W3 = 0, *b3 = 0, *lin_w = 0, *lin_b = 0;
    int nb = 0, nw = 0;
    for (int i = 0; i < n_in; ++i) {
        const float* p = (const float*)d_in[i];
        switch (in_sizes[i]) {
            case NN * FF:            x = p;    break;
            case NN * NN:            adj = p;  break;
            case (NN * (NN + 1)) / 2: pvec = p; break;
            case FF * HH:            W1 = p;   break;
            case HH * HH:
                if (nw == 0) W2 = p; else W3 = p;
                ++nw; break;
            case HH:
                if (nb == 0) b1 = p; else if (nb == 1) b2 = p; else b3 = p;
                ++nb; break;
            case HH * CC:            lin_w = p; break;
            case CC:                 lin_b = p; break;
            default: break;
        }
    }
    float* out = (float*)d_out;

    k_build<<<NN / 8, 256>>>(adj, pvec);       // 1 warp/row; accumulates g_deg
    k_xw<<<NN / 32, 256>>>(x, W1);             // g_Ta = x@W1 (+ dis finalize)
    k_norm<<<NN * 16 / 256, 256>>>();          // fold D^{-1/2} into edges
    k_layer<<<NN / 8, 512>>>(0, b1, W2);       // g_Ta -> g_Tb
    k_layer<<<NN / 8, 512>>>(1, b2, W3);       // g_Tb -> g_Ta
    k_final<<<NN / 8, 512>>>(b3, lin_w, lin_b, out);
}